// round 10
// baseline (speedup 1.0000x reference)
#include <cuda_runtime.h>
#include <stdint.h>
#include <math.h>

#define D        512
#define NCHUNK   16
#define BMAX     16
#define NEG_INF  -1e30f

#define ROWB     2048                 // bytes per value row (D*4)
#define GROWS    16                   // rows per pipeline group
#define STAGEB   (GROWS * ROWB)       // 32768 bytes per stage
#define RINGB    (2 * STAGEB)         // 65536

// dynamic smem layout (bytes)
#define OFF_IDX   65536
#define OFF_POP   67584
#define OFF_OFFS  67648
#define OFF_TOT   67712
#define OFF_SMM   67776
#define OFF_SMS   67808
#define OFF_SE    67840
#define OFF_SINV  67904
#define OFF_VEC   67968
#define OFF_Q     70016
#define OFF_CTX   72064
#define SMEM_TOTAL (72064 + 8 * D * 4)   // 88448

// ---------------- scratch (no allocation allowed) ----------------
__device__ float g_q[BMAX * D];
__device__ float g_pm[BMAX * NCHUNK];
__device__ float g_ps[BMAX * NCHUNK];
__device__ float g_pctx[BMAX * NCHUNK * D];
__device__ unsigned long long g_bar = 0;

// Replay-safe grid barrier (monotonic ticket counter).
__device__ __forceinline__ void grid_barrier()
{
    __syncthreads();
    if (threadIdx.x == 0) {
        __threadfence();
        const unsigned long long g = gridDim.x;
        unsigned long long t = atomicAdd(&g_bar, 1ULL);
        unsigned long long target = (t / g + 1ULL) * g;
        volatile unsigned long long* p = &g_bar;
        while (*p < target) __nanosleep(64);
        __threadfence();
    }
    __syncthreads();
}

__device__ __forceinline__ void cp_async16(uint32_t dst_smem, const void* src)
{
    asm volatile("cp.async.cg.shared.global [%0], [%1], 16;\n"
                 :: "r"(dst_smem), "l"(src));
}

// ---------------- fused kernel: qproj -> attention -> output ----------------
// grid = B*NCHUNK = 256 blocks, block = 256 (8 warps), ~88KB dyn smem (2/SM).
__global__ void __launch_bounds__(256) fused_attn(
    const float* __restrict__ query,
    const float* __restrict__ value,
    const int*   __restrict__ mask,
    const float* __restrict__ W_align,
    const float* __restrict__ b_align,
    const float* __restrict__ W_query,
    const float* __restrict__ b_query,
    const float* __restrict__ W_value,
    const float* __restrict__ b_value,
    float* __restrict__ out,
    int L)
{
    extern __shared__ char smem[];
    const int bid  = blockIdx.x;
    const int b    = bid >> 4;
    const int seg  = bid & 15;
    const int tid  = threadIdx.x;
    const int warp = tid >> 5;
    const int lane = tid & 31;

    float* s_vec = reinterpret_cast<float*>(smem + OFF_VEC);
    float* s_q   = reinterpret_cast<float*>(smem + OFF_Q);
    int*   s_idx = reinterpret_cast<int*>  (smem + OFF_IDX);
    int*   s_pop = reinterpret_cast<int*>  (smem + OFF_POP);
    int*   s_off = reinterpret_cast<int*>  (smem + OFF_OFFS);
    int*   s_tot = reinterpret_cast<int*>  (smem + OFF_TOT);
    float* sm_m  = reinterpret_cast<float*>(smem + OFF_SMM);
    float* sm_s  = reinterpret_cast<float*>(smem + OFF_SMS);
    float* s_e   = reinterpret_cast<float*>(smem + OFF_SE);
    float* s_Sinv= reinterpret_cast<float*>(smem + OFF_SINV);
    float* sm_ctx= reinterpret_cast<float*>(smem + OFF_CTX);   // [8][D]

    const uint32_t ring_u32 =
        (uint32_t)__cvta_generic_to_shared(smem);   // ring at offset 0

    // ================= Phase 1: q = query @ W_align^T + b_align ===========
    for (int i = tid; i < D; i += 256) s_vec[i] = query[(size_t)b * D + i];
    __syncthreads();
    {
        const int d0 = seg * 32 + warp * 4;
        const float4* x4 = reinterpret_cast<const float4*>(s_vec);
        float4 x[4];
#pragma unroll
        for (int k = 0; k < 4; k++) x[k] = x4[lane + 32 * k];

        float acc[4] = {0.f, 0.f, 0.f, 0.f};
#pragma unroll
        for (int i = 0; i < 4; i++) {
            const float4* wrow = reinterpret_cast<const float4*>(W_align + (size_t)(d0 + i) * D);
#pragma unroll
            for (int k = 0; k < 4; k++) {
                float4 w = wrow[lane + 32 * k];
                acc[i] = fmaf(w.x, x[k].x, acc[i]); acc[i] = fmaf(w.y, x[k].y, acc[i]);
                acc[i] = fmaf(w.z, x[k].z, acc[i]); acc[i] = fmaf(w.w, x[k].w, acc[i]);
            }
        }
#pragma unroll
        for (int o = 16; o > 0; o >>= 1) {
#pragma unroll
            for (int i = 0; i < 4; i++) acc[i] += __shfl_xor_sync(0xffffffffu, acc[i], o);
        }
        if (lane < 4)
            g_q[(size_t)b * D + d0 + lane] = acc[lane] + b_align[d0 + lane];
    }

    grid_barrier();

    // ================= Phase 2: online-softmax over value (cp.async) =======
    {
        const int RC = L / NCHUNK;          // 512
        const int l0 = seg * RC;

        // ---- compact unmasked row indices ----
        const int* mrow = mask + (size_t)b * L + l0;
        unsigned a0 = __ballot_sync(0xffffffffu, mrow[tid]       == 0);
        unsigned a1 = __ballot_sync(0xffffffffu, mrow[tid + 256] == 0);
        if (lane == 0) { s_pop[warp] = __popc(a0); s_pop[warp + 8] = __popc(a1); }
        __syncthreads();
        if (tid == 0) {
            int acc = 0;
#pragma unroll
            for (int i = 0; i < 16; i++) { s_off[i] = acc; acc += s_pop[i]; }
            s_tot[0] = acc;
        }
        __syncthreads();
        if ((a0 >> lane) & 1)
            s_idx[s_off[warp]     + __popc(a0 & ((1u << lane) - 1))] = warp * 32 + lane;
        if ((a1 >> lane) & 1)
            s_idx[s_off[warp + 8] + __popc(a1 & ((1u << lane) - 1))] = 256 + warp * 32 + lane;
        __syncthreads();
        const int T = s_tot[0];
        const int ngroups = (T + GROWS - 1) / GROWS;

        const char* vbase = reinterpret_cast<const char*>(value + ((size_t)b * L + l0) * D);

        // producer: stage group g into ring slot g&1 (all 256 threads)
        auto prefetch = [&](int g) {
            if (g < ngroups) {
                const int t0 = g * GROWS;
                const uint32_t dst0 = ring_u32 + (g & 1) * STAGEB;
#pragma unroll
                for (int i = 0; i < 8; i++) {
                    const int c   = tid + 256 * i;      // chunk id 0..2047
                    const int r   = c >> 7;             // row slot 0..15
                    const int off = (c & 127) * 16;     // byte offset in row
                    if (t0 + r < T) {
                        const char* src = vbase + (size_t)s_idx[t0 + r] * ROWB + off;
                        cp_async16(dst0 + r * ROWB + off, src);
                    }
                }
            }
            asm volatile("cp.async.commit_group;\n" ::);
        };

        // q into registers
        const float4* q4 = reinterpret_cast<const float4*>(g_q + b * D);
        float4 q[4];
#pragma unroll
        for (int k = 0; k < 4; k++) q[k] = q4[lane + 32 * k];

        float m = NEG_INF, s = 0.f;
        float4 ctx[4];
#pragma unroll
        for (int k = 0; k < 4; k++) ctx[k] = make_float4(0.f, 0.f, 0.f, 0.f);

        prefetch(0);
        prefetch(1);

        for (int g = 0; g < ngroups; g++) {
            asm volatile("cp.async.wait_group 1;\n" ::);
            __syncthreads();

            // consume: warp w takes row slots 2w, 2w+1 of this stage
            const float* stage = reinterpret_cast<const float*>(smem + (g & 1) * STAGEB);
            const int t0 = g * GROWS;
            const int rA = t0 + 2 * warp;
            const int rB = rA + 1;
            const bool vA = rA < T, vB = rB < T;
            const float4* pa = reinterpret_cast<const float4*>(stage + (vA ? 2 * warp     : 0) * D);
            const float4* pb = reinterpret_cast<const float4*>(stage + (vB ? 2 * warp + 1 : 0) * D);

            float4 va[4], vb[4];
#pragma unroll
            for (int k = 0; k < 4; k++) va[k] = pa[lane + 32 * k];
#pragma unroll
            for (int k = 0; k < 4; k++) vb[k] = pb[lane + 32 * k];

            float sA = 0.f, sB = 0.f;
#pragma unroll
            for (int k = 0; k < 4; k++) {
                sA = fmaf(va[k].x, q[k].x, sA); sA = fmaf(va[k].y, q[k].y, sA);
                sA = fmaf(va[k].z, q[k].z, sA); sA = fmaf(va[k].w, q[k].w, sA);
                sB = fmaf(vb[k].x, q[k].x, sB); sB = fmaf(vb[k].y, q[k].y, sB);
                sB = fmaf(vb[k].z, q[k].z, sB); sB = fmaf(vb[k].w, q[k].w, sB);
            }
#pragma unroll
            for (int o = 16; o > 0; o >>= 1) {
                sA += __shfl_xor_sync(0xffffffffu, sA, o);
                sB += __shfl_xor_sync(0xffffffffu, sB, o);
            }
            if (!vA) sA = NEG_INF;
            if (!vB) sB = NEG_INF;

            const float m_new = fmaxf(m, fmaxf(sA, sB));
            const float corr  = __expf(m  - m_new);
            const float wa    = __expf(sA - m_new);
            const float wb    = __expf(sB - m_new);
            s = s * corr + wa + wb;
#pragma unroll
            for (int k = 0; k < 4; k++) {
                ctx[k].x = ctx[k].x * corr + fmaf(wa, va[k].x, wb * vb[k].x);
                ctx[k].y = ctx[k].y * corr + fmaf(wa, va[k].y, wb * vb[k].y);
                ctx[k].z = ctx[k].z * corr + fmaf(wa, va[k].z, wb * vb[k].z);
                ctx[k].w = ctx[k].w * corr + fmaf(wa, va[k].w, wb * vb[k].w);
            }
            m = m_new;

            __syncthreads();            // stage fully consumed
            prefetch(g + 2);            // refill this slot (always commits)
        }

        // ---- merge the 8 warps' partials ----
        if (lane == 0) { sm_m[warp] = m; sm_s[warp] = s; }
#pragma unroll
        for (int k = 0; k < 4; k++) {
            const int i = (lane + 32 * k) * 4;
            sm_ctx[warp * D + i + 0] = ctx[k].x;
            sm_ctx[warp * D + i + 1] = ctx[k].y;
            sm_ctx[warp * D + i + 2] = ctx[k].z;
            sm_ctx[warp * D + i + 3] = ctx[k].w;
        }
        __syncthreads();

        float M = NEG_INF;
#pragma unroll
        for (int wi = 0; wi < 8; wi++) M = fmaxf(M, sm_m[wi]);
        float e[8];
#pragma unroll
        for (int wi = 0; wi < 8; wi++) e[wi] = __expf(sm_m[wi] - M);

        float o0 = 0.f, o1 = 0.f;
#pragma unroll
        for (int wi = 0; wi < 8; wi++) {
            o0 = fmaf(sm_ctx[wi * D + tid],       e[wi], o0);
            o1 = fmaf(sm_ctx[wi * D + tid + 256], e[wi], o1);
        }
        const int pidx = b * NCHUNK + seg;
        g_pctx[(size_t)pidx * D + tid]       = o0;
        g_pctx[(size_t)pidx * D + tid + 256] = o1;

        if (tid == 0) {
            float S = 0.f;
#pragma unroll
            for (int wi = 0; wi < 8; wi++) S = fmaf(sm_s[wi], e[wi], S);
            g_pm[pidx] = M;
            g_ps[pidx] = S;
        }
    }

    grid_barrier();

    // ================= Phase 3: combine + dual GEMV + tanh =================
    {
        if (warp == 0) {
            float mv = (lane < NCHUNK) ? g_pm[b * NCHUNK + lane] : NEG_INF;
            float M = mv;
#pragma unroll
            for (int o = 16; o > 0; o >>= 1) M = fmaxf(M, __shfl_xor_sync(0xffffffffu, M, o));
            float e  = (lane < NCHUNK) ? __expf(mv - M) : 0.f;
            float Sp = (lane < NCHUNK) ? g_ps[b * NCHUNK + lane] * e : 0.f;
#pragma unroll
            for (int o = 16; o > 0; o >>= 1) Sp += __shfl_xor_sync(0xffffffffu, Sp, o);
            if (lane < NCHUNK) s_e[lane] = e;
            if (lane == 0) s_Sinv[0] = 1.f / Sp;
        }
        __syncthreads();

        const float Sinv = s_Sinv[0];
#pragma unroll
        for (int r = 0; r < 2; r++) {
            const int d = tid + 256 * r;
            const float* pc = g_pctx + (size_t)b * NCHUNK * D + d;
            float acc = 0.f;
#pragma unroll
            for (int c = 0; c < NCHUNK; c++)
                acc = fmaf(pc[(size_t)c * D], s_e[c], acc);
            s_vec[d] = acc * Sinv;
            s_q[d]   = g_q[(size_t)b * D + d];
        }
        __syncthreads();

        const int d0 = seg * 32 + warp * 4;
        const float4* c4 = reinterpret_cast<const float4*>(s_vec);
        const float4* q4 = reinterpret_cast<const float4*>(s_q);
        float4 cx[4], qx[4];
#pragma unroll
        for (int k = 0; k < 4; k++) { cx[k] = c4[lane + 32 * k]; qx[k] = q4[lane + 32 * k]; }

        float acc[4] = {0.f, 0.f, 0.f, 0.f};
#pragma unroll
        for (int i = 0; i < 4; i++) {
            const float4* wv = reinterpret_cast<const float4*>(W_value + (size_t)(d0 + i) * D);
            const float4* wq = reinterpret_cast<const float4*>(W_query + (size_t)(d0 + i) * D);
#pragma unroll
            for (int k = 0; k < 4; k++) {
                float4 a = wv[lane + 32 * k];
                float4 g = wq[lane + 32 * k];
                acc[i] = fmaf(a.x, cx[k].x, acc[i]); acc[i] = fmaf(a.y, cx[k].y, acc[i]);
                acc[i] = fmaf(a.z, cx[k].z, acc[i]); acc[i] = fmaf(a.w, cx[k].w, acc[i]);
                acc[i] = fmaf(g.x, qx[k].x, acc[i]); acc[i] = fmaf(g.y, qx[k].y, acc[i]);
                acc[i] = fmaf(g.z, qx[k].z, acc[i]); acc[i] = fmaf(g.w, qx[k].w, acc[i]);
            }
        }
#pragma unroll
        for (int o = 16; o > 0; o >>= 1) {
#pragma unroll
            for (int i = 0; i < 4; i++) acc[i] += __shfl_xor_sync(0xffffffffu, acc[i], o);
        }
        if (lane < 4) {
            const int d = d0 + lane;
            out[(size_t)b * D + d] = tanhf(acc[lane] + b_value[d] + b_query[d]);
        }
    }
}

// ---------------- launch ----------------
extern "C" void kernel_launch(void* const* d_in, const int* in_sizes, int n_in,
                              void* d_out, int out_size)
{
    const float* query   = (const float*)d_in[0];
    const float* value   = (const float*)d_in[1];
    const int*   mask    = (const int*)  d_in[2];
    const float* W_align = (const float*)d_in[3];
    const float* b_align = (const float*)d_in[4];
    const float* W_query = (const float*)d_in[5];
    const float* b_query = (const float*)d_in[6];
    const float* W_value = (const float*)d_in[7];
    const float* b_value = (const float*)d_in[8];
    float* out = (float*)d_out;

    const int B = in_sizes[0] / D;          // 16
    const int L = in_sizes[2] / B;          // 8192

    cudaFuncSetAttribute(fused_attn,
                         cudaFuncAttributeMaxDynamicSharedMemorySize, SMEM_TOTAL);

    fused_attn<<<B * NCHUNK, 256, SMEM_TOTAL>>>(query, value, mask,
                                                W_align, b_align,
                                                W_query, b_query,
                                                W_value, b_value, out, L);
}

// round 11
// speedup vs baseline: 1.0481x; 1.0481x over previous
#include <cuda_runtime.h>
#include <stdint.h>
#include <math.h>

#define D        512
#define NCHUNK   16
#define BMAX     16
#define NEG_INF  -1e30f

// ---------------- scratch (no allocation allowed) ----------------
__device__ float g_q[BMAX * D];
__device__ float g_pm[BMAX * NCHUNK];
__device__ float g_ps[BMAX * NCHUNK];
__device__ float g_pctx[BMAX * NCHUNK * D];
__device__ float g_ctx[BMAX * D];
__device__ unsigned long long g_bar = 0;

// Replay-safe grid barrier (monotonic ticket counter).
__device__ __forceinline__ void grid_barrier()
{
    __syncthreads();
    if (threadIdx.x == 0) {
        __threadfence();
        const unsigned long long g = gridDim.x;
        unsigned long long t = atomicAdd(&g_bar, 1ULL);
        unsigned long long target = (t / g + 1ULL) * g;
        volatile unsigned long long* p = &g_bar;
        while (*p < target) __nanosleep(64);
        __threadfence();
    }
    __syncthreads();
}

__device__ __forceinline__ float dot4(const float4 a, const float4 b)
{
    float r;
    r = a.x * b.x;
    r = fmaf(a.y, b.y, r);
    r = fmaf(a.z, b.z, r);
    r = fmaf(a.w, b.w, r);
    return r;
}

// ---------------- fused kernel ----------------
// grid = 256 blocks (= B*NCHUNK = D/2), block = 256 (8 warps), 2 blocks/SM.
__global__ void __launch_bounds__(256, 2) fused_attn(
    const float* __restrict__ query,
    const float* __restrict__ value,
    const int*   __restrict__ mask,
    const float* __restrict__ W_align,
    const float* __restrict__ b_align,
    const float* __restrict__ W_query,
    const float* __restrict__ b_query,
    const float* __restrict__ W_value,
    const float* __restrict__ b_value,
    float* __restrict__ out,
    int L)
{
    const int bid  = blockIdx.x;
    const int tid  = threadIdx.x;
    const int warp = tid >> 5;
    const int lane = tid & 31;

    __shared__ int   s_idx[512];
    __shared__ int   s_pop[16], s_off[16], s_tot;
    __shared__ float sm_m[8], sm_s[8];
    __shared__ float sm_ctx[8][D];          // P2 warp partials; P2.5 partial sums
    __shared__ float s_e[NCHUNK];
    __shared__ float s_Sinv;

    // ================= Phase 1: q = query @ W_align^T + b_align ===========
    // block = d-pair (d0, d0+1); warp w = batches (2w, 2w+1). W read ONCE.
    {
        const int d0 = bid * 2;
        const float4* w0p = reinterpret_cast<const float4*>(W_align + (size_t)d0 * D);
        const float4* w1p = reinterpret_cast<const float4*>(W_align + (size_t)(d0 + 1) * D);
        float4 w0[4], w1[4];
#pragma unroll
        for (int k = 0; k < 4; k++) { w0[k] = w0p[lane + 32 * k]; w1[k] = w1p[lane + 32 * k]; }

        float a00 = 0.f, a01 = 0.f, a10 = 0.f, a11 = 0.f;
        {
            const float4* x0 = reinterpret_cast<const float4*>(query + (size_t)(2 * warp) * D);
            const float4* x1 = reinterpret_cast<const float4*>(query + (size_t)(2 * warp + 1) * D);
#pragma unroll
            for (int k = 0; k < 4; k++) {
                float4 xa = x0[lane + 32 * k];
                float4 xb = x1[lane + 32 * k];
                a00 += dot4(w0[k], xa); a01 += dot4(w0[k], xb);
                a10 += dot4(w1[k], xa); a11 += dot4(w1[k], xb);
            }
        }
#pragma unroll
        for (int o = 16; o > 0; o >>= 1) {
            a00 += __shfl_xor_sync(0xffffffffu, a00, o);
            a01 += __shfl_xor_sync(0xffffffffu, a01, o);
            a10 += __shfl_xor_sync(0xffffffffu, a10, o);
            a11 += __shfl_xor_sync(0xffffffffu, a11, o);
        }
        if (lane < 4) {
            const int dd = d0 + (lane >> 1);
            const int bb = 2 * warp + (lane & 1);
            const float r = (lane == 0) ? a00 : (lane == 1) ? a01 : (lane == 2) ? a10 : a11;
            g_q[(size_t)bb * D + dd] = r + b_align[dd];
        }
    }

    grid_barrier();

    // ================= Phase 2: online-softmax over value (R8 version) =====
    const int b   = bid >> 4;
    const int seg = bid & 15;
    {
        const int RC = L / NCHUNK;          // 512
        const int l0 = seg * RC;

        // ---- compact unmasked row indices ----
        const int* mrow = mask + (size_t)b * L + l0;
        unsigned a0 = __ballot_sync(0xffffffffu, mrow[tid]       == 0);
        unsigned a1 = __ballot_sync(0xffffffffu, mrow[tid + 256] == 0);
        if (lane == 0) { s_pop[warp] = __popc(a0); s_pop[warp + 8] = __popc(a1); }
        __syncthreads();
        if (tid == 0) {
            int acc = 0;
#pragma unroll
            for (int i = 0; i < 16; i++) { s_off[i] = acc; acc += s_pop[i]; }
            s_tot = acc;
        }
        __syncthreads();
        if ((a0 >> lane) & 1)
            s_idx[s_off[warp]     + __popc(a0 & ((1u << lane) - 1))] = warp * 32 + lane;
        if ((a1 >> lane) & 1)
            s_idx[s_off[warp + 8] + __popc(a1 & ((1u << lane) - 1))] = 256 + warp * 32 + lane;
        __syncthreads();
        const int T = s_tot;

        const float4* q4 = reinterpret_cast<const float4*>(g_q + b * D);
        float4 q[4];
#pragma unroll
        for (int k = 0; k < 4; k++) q[k] = q4[lane + 32 * k];

        float m = NEG_INF, s = 0.f;
        float4 ctx[4];
#pragma unroll
        for (int k = 0; k < 4; k++) ctx[k] = make_float4(0.f, 0.f, 0.f, 0.f);

        const float* vbase = value + ((size_t)b * L + l0) * D;

        for (int t0 = warp * 4; t0 < T; t0 += 32) {
            const int n = min(4, T - t0);
            const int j0 = s_idx[t0];
            const int j1 = s_idx[t0 + (n > 1 ? 1 : 0)];
            const int j2 = s_idx[t0 + (n > 2 ? 2 : 0)];
            const int j3 = s_idx[t0 + (n > 3 ? 3 : 0)];

            const float4* p0 = reinterpret_cast<const float4*>(vbase + (size_t)j0 * D);
            const float4* p1 = reinterpret_cast<const float4*>(vbase + (size_t)j1 * D);
            const float4* p2 = reinterpret_cast<const float4*>(vbase + (size_t)j2 * D);
            const float4* p3 = reinterpret_cast<const float4*>(vbase + (size_t)j3 * D);

            float4 v0[4], v1[4], v2[4], v3[4];
#pragma unroll
            for (int k = 0; k < 4; k++) v0[k] = __ldcs(p0 + lane + 32 * k);
#pragma unroll
            for (int k = 0; k < 4; k++) v1[k] = __ldcs(p1 + lane + 32 * k);
#pragma unroll
            for (int k = 0; k < 4; k++) v2[k] = __ldcs(p2 + lane + 32 * k);
#pragma unroll
            for (int k = 0; k < 4; k++) v3[k] = __ldcs(p3 + lane + 32 * k);

            float s0 = 0.f, s1 = 0.f, s2 = 0.f, s3 = 0.f;
#pragma unroll
            for (int k = 0; k < 4; k++) {
                s0 += dot4(v0[k], q[k]);
                s1 += dot4(v1[k], q[k]);
                s2 += dot4(v2[k], q[k]);
                s3 += dot4(v3[k], q[k]);
            }
#pragma unroll
            for (int o = 16; o > 0; o >>= 1) {
                s0 += __shfl_xor_sync(0xffffffffu, s0, o);
                s1 += __shfl_xor_sync(0xffffffffu, s1, o);
                s2 += __shfl_xor_sync(0xffffffffu, s2, o);
                s3 += __shfl_xor_sync(0xffffffffu, s3, o);
            }
            if (n < 2) s1 = NEG_INF;
            if (n < 3) s2 = NEG_INF;
            if (n < 4) s3 = NEG_INF;

            const float m_new = fmaxf(fmaxf(m, fmaxf(s0, s1)), fmaxf(s2, s3));
            const float corr = __expf(m  - m_new);
            const float w0   = __expf(s0 - m_new);
            const float w1   = __expf(s1 - m_new);
            const float w2   = __expf(s2 - m_new);
            const float w3   = __expf(s3 - m_new);
            s = s * corr + w0 + w1 + w2 + w3;
#pragma unroll
            for (int k = 0; k < 4; k++) {
                ctx[k].x = ctx[k].x * corr + fmaf(w1, v1[k].x, w0 * v0[k].x)
                                           + fmaf(w3, v3[k].x, w2 * v2[k].x);
                ctx[k].y = ctx[k].y * corr + fmaf(w1, v1[k].y, w0 * v0[k].y)
                                           + fmaf(w3, v3[k].y, w2 * v2[k].y);
                ctx[k].z = ctx[k].z * corr + fmaf(w1, v1[k].z, w0 * v0[k].z)
                                           + fmaf(w3, v3[k].z, w2 * v2[k].z);
                ctx[k].w = ctx[k].w * corr + fmaf(w1, v1[k].w, w0 * v0[k].w)
                                           + fmaf(w3, v3[k].w, w2 * v2[k].w);
            }
            m = m_new;
        }

        // ---- merge the 8 warps' partials ----
        if (lane == 0) { sm_m[warp] = m; sm_s[warp] = s; }
#pragma unroll
        for (int k = 0; k < 4; k++) {
            const int i = (lane + 32 * k) * 4;
            sm_ctx[warp][i + 0] = ctx[k].x;
            sm_ctx[warp][i + 1] = ctx[k].y;
            sm_ctx[warp][i + 2] = ctx[k].z;
            sm_ctx[warp][i + 3] = ctx[k].w;
        }
        __syncthreads();

        float M = NEG_INF;
#pragma unroll
        for (int wi = 0; wi < 8; wi++) M = fmaxf(M, sm_m[wi]);
        float e[8];
#pragma unroll
        for (int wi = 0; wi < 8; wi++) e[wi] = __expf(sm_m[wi] - M);

        float o0 = 0.f, o1 = 0.f;
#pragma unroll
        for (int wi = 0; wi < 8; wi++) {
            o0 = fmaf(sm_ctx[wi][tid],       e[wi], o0);
            o1 = fmaf(sm_ctx[wi][tid + 256], e[wi], o1);
        }
        const int pidx = b * NCHUNK + seg;
        g_pctx[(size_t)pidx * D + tid]       = o0;
        g_pctx[(size_t)pidx * D + tid + 256] = o1;

        if (tid == 0) {
            float S = 0.f;
#pragma unroll
            for (int wi = 0; wi < 8; wi++) S = fmaf(sm_s[wi], e[wi], S);
            g_pm[pidx] = M;
            g_ps[pidx] = S;
        }
    }

    grid_barrier();

    // ================= Phase 2.5: combine chunk partials -> g_ctx ==========
    // Block (b, seg) produces g_ctx[b, seg*32 .. seg*32+32).
    {
        __syncthreads();   // re-use of sm_ctx below
        if (warp == 0) {
            float mv = (lane < NCHUNK) ? g_pm[b * NCHUNK + lane] : NEG_INF;
            float M = mv;
#pragma unroll
            for (int o = 16; o > 0; o >>= 1) M = fmaxf(M, __shfl_xor_sync(0xffffffffu, M, o));
            float e  = (lane < NCHUNK) ? __expf(mv - M) : 0.f;
            float Sp = (lane < NCHUNK) ? g_ps[b * NCHUNK + lane] * e : 0.f;
#pragma unroll
            for (int o = 16; o > 0; o >>= 1) Sp += __shfl_xor_sync(0xffffffffu, Sp, o);
            if (lane < NCHUNK) s_e[lane] = e;
            if (lane == 0) s_Sinv = 1.f / Sp;
        }
        __syncthreads();

        // thread t: d-col (t&31), chunk pair (t>>5)
        const int dcol = tid & 31;
        const int cp   = tid >> 5;           // 0..7
        const int dgl  = seg * 32 + dcol;
        const float* pc = g_pctx + (size_t)b * NCHUNK * D + dgl;
        float part = pc[(size_t)(2 * cp) * D]     * s_e[2 * cp]
                   + pc[(size_t)(2 * cp + 1) * D] * s_e[2 * cp + 1];
        sm_ctx[cp][dcol] = part;
        __syncthreads();
        if (tid < 32) {
            float acc = 0.f;
#pragma unroll
            for (int i = 0; i < 8; i++) acc += sm_ctx[i][tid];
            g_ctx[(size_t)b * D + seg * 32 + tid] = acc * s_Sinv;
        }
    }

    grid_barrier();

    // ================= Phase 3: out = tanh(ctx@Wv^T + q@Wq^T + biases) =====
    // block = d-pair (d0, d0+1); warp w = batches (2w, 2w+1). W read ONCE.
    {
        const int d0 = bid * 2;
        const float4* wv0p = reinterpret_cast<const float4*>(W_value + (size_t)d0 * D);
        const float4* wv1p = reinterpret_cast<const float4*>(W_value + (size_t)(d0 + 1) * D);
        const float4* wq0p = reinterpret_cast<const float4*>(W_query + (size_t)d0 * D);
        const float4* wq1p = reinterpret_cast<const float4*>(W_query + (size_t)(d0 + 1) * D);
        float4 wv0[4], wv1[4], wq0[4], wq1[4];
#pragma unroll
        for (int k = 0; k < 4; k++) {
            wv0[k] = wv0p[lane + 32 * k]; wv1[k] = wv1p[lane + 32 * k];
            wq0[k] = wq0p[lane + 32 * k]; wq1[k] = wq1p[lane + 32 * k];
        }

        float a00 = 0.f, a01 = 0.f, a10 = 0.f, a11 = 0.f;
#pragma unroll
        for (int jb = 0; jb < 2; jb++) {
            const int bb = 2 * warp + jb;
            const float4* cxp = reinterpret_cast<const float4*>(g_ctx + (size_t)bb * D);
            const float4* qxp = reinterpret_cast<const float4*>(g_q   + (size_t)bb * D);
            float r0 = 0.f, r1 = 0.f;
#pragma unroll
            for (int k = 0; k < 4; k++) {
                float4 cx = cxp[lane + 32 * k];
                float4 qx = qxp[lane + 32 * k];
                r0 += dot4(wv0[k], cx); r0 += dot4(wq0[k], qx);
                r1 += dot4(wv1[k], cx); r1 += dot4(wq1[k], qx);
            }
            if (jb == 0) { a00 = r0; a10 = r1; }
            else         { a01 = r0; a11 = r1; }
        }
#pragma unroll
        for (int o = 16; o > 0; o >>= 1) {
            a00 += __shfl_xor_sync(0xffffffffu, a00, o);
            a01 += __shfl_xor_sync(0xffffffffu, a01, o);
            a10 += __shfl_xor_sync(0xffffffffu, a10, o);
            a11 += __shfl_xor_sync(0xffffffffu, a11, o);
        }
        if (lane < 4) {
            const int dd = d0 + (lane >> 1);
            const int bb = 2 * warp + (lane & 1);
            const float r = (lane == 0) ? a00 : (lane == 1) ? a01 : (lane == 2) ? a10 : a11;
            out[(size_t)bb * D + dd] = tanhf(r + b_value[dd] + b_query[dd]);
        }
    }
}

// ---------------- launch ----------------
extern "C" void kernel_launch(void* const* d_in, const int* in_sizes, int n_in,
                              void* d_out, int out_size)
{
    const float* query   = (const float*)d_in[0];
    const float* value   = (const float*)d_in[1];
    const int*   mask    = (const int*)  d_in[2];
    const float* W_align = (const float*)d_in[3];
    const float* b_align = (const float*)d_in[4];
    const float* W_query = (const float*)d_in[5];
    const float* b_query = (const float*)d_in[6];
    const float* W_value = (const float*)d_in[7];
    const float* b_value = (const float*)d_in[8];
    float* out = (float*)d_out;

    const int B = in_sizes[0] / D;          // 16
    const int L = in_sizes[2] / B;          // 8192

    fused_attn<<<B * NCHUNK, 256>>>(query, value, mask,
                                    W_align, b_align, W_query, b_query,
                                    W_value, b_value, out, L);
}